// round 2
// baseline (speedup 1.0000x reference)
#include <cuda_runtime.h>
#include <cuda_bf16.h>
#include <math.h>

// ---------------- problem constants ----------------
#define NTOK 16384      // B*T = 4*4096
#define HDIM 1024
#define NEXP 8
#define TOPK 2
#define FDIM 1024

#define TM 64
#define TN 64
#define KB 16

#define NASSIGN (NTOK * TOPK)                 // 32768 (exact)
#define PADDED_CAP (NASSIGN + NEXP * TM)      // 33280 (per-expert 64-align pad)

// ---------------- device scratch (static; no allocs) ----------------
__device__ float g_hid[(size_t)PADDED_CAP * FDIM];      // SwiGLU hidden, per assignment row
__device__ float g_contrib[(size_t)PADDED_CAP * HDIM];  // scaled expert output, per row
__device__ int   g_perm[PADDED_CAP];                    // row -> token (-1 = pad)
__device__ float g_gw[PADDED_CAP];                      // row -> gate weight
__device__ int   g_rowof[NTOK * TOPK];                  // (token,k) -> row
__device__ int   g_tok_e[NTOK * TOPK];
__device__ float g_tok_w[NTOK * TOPK];
__device__ int   g_count[NEXP];
__device__ int   g_cursor[NEXP];
__device__ float g_usage[NEXP];
__device__ int   g_offset[NEXP + 1];

// ---------------- K0: init ----------------
__global__ void init_kernel() {
    int idx = blockIdx.x * blockDim.x + threadIdx.x;
    if (idx < PADDED_CAP) g_perm[idx] = -1;
    if (idx < NEXP) { g_count[idx] = 0; g_cursor[idx] = 0; g_usage[idx] = 0.f; }
}

// ---------------- K1: router (4 tokens/block, warp per token) ----------------
__global__ __launch_bounds__(128) void router_kernel(const float* __restrict__ x,
                                                     const float* __restrict__ rw) {
    __shared__ float srw[NEXP * HDIM];   // 32KB
    __shared__ float sprob[NEXP];
    int tid = threadIdx.x;
    for (int i = tid; i < NEXP * HDIM; i += 128) srw[i] = rw[i];
    if (tid < NEXP) sprob[tid] = 0.f;
    __syncthreads();

    int warp = tid >> 5, lane = tid & 31;
    int t = blockIdx.x * 4 + warp;

    float acc[NEXP];
#pragma unroll
    for (int e = 0; e < NEXP; e++) acc[e] = 0.f;

    const float* xp = x + (size_t)t * HDIM;
    for (int j = lane; j < HDIM; j += 32) {
        float xv = xp[j];
#pragma unroll
        for (int e = 0; e < NEXP; e++) acc[e] += xv * srw[e * HDIM + j];
    }
#pragma unroll
    for (int e = 0; e < NEXP; e++) {
#pragma unroll
        for (int off = 16; off; off >>= 1)
            acc[e] += __shfl_xor_sync(0xFFFFFFFFu, acc[e], off);
    }

    if (lane == 0) {
        float mx = acc[0];
#pragma unroll
        for (int e = 1; e < NEXP; e++) mx = fmaxf(mx, acc[e]);
        float p[NEXP]; float s = 0.f;
#pragma unroll
        for (int e = 0; e < NEXP; e++) { p[e] = expf(acc[e] - mx); s += p[e]; }
        float inv = 1.f / s;
#pragma unroll
        for (int e = 0; e < NEXP; e++) p[e] *= inv;

        // top-2 (stable: earliest index wins ties, matching sorted-descending top_k)
        int e1 = 0;
#pragma unroll
        for (int e = 1; e < NEXP; e++) if (p[e] > p[e1]) e1 = e;
        int e2 = (e1 == 0) ? 1 : 0;
#pragma unroll
        for (int e = 0; e < NEXP; e++) if (e != e1 && p[e] > p[e2]) e2 = e;

        float ws = p[e1] + p[e2];
        g_tok_e[2 * t + 0] = e1; g_tok_w[2 * t + 0] = p[e1] / ws;
        g_tok_e[2 * t + 1] = e2; g_tok_w[2 * t + 1] = p[e2] / ws;
        atomicAdd(&g_count[e1], 1);
        atomicAdd(&g_count[e2], 1);
#pragma unroll
        for (int e = 0; e < NEXP; e++) atomicAdd(&sprob[e], p[e]);
    }
    __syncthreads();
    if (tid < NEXP) atomicAdd(&g_usage[tid], sprob[tid]);
}

// ---------------- K2: scan + lb_loss ----------------
__global__ void scan_kernel(float* lb_out, int write_lb) {
    int off = 0;
    for (int e = 0; e < NEXP; e++) {
        g_offset[e] = off;
        off += ((g_count[e] + TM - 1) / TM) * TM;
    }
    g_offset[NEXP] = off;
    if (write_lb) {
        float s = 0.f;
        for (int e = 0; e < NEXP; e++) {
            float u = g_usage[e] / (float)NTOK;
            s += u * u;
        }
        *lb_out = 0.01f * (float)NEXP * s;
    }
}

// ---------------- K3: placement ----------------
__global__ void place_kernel() {
    int t = blockIdx.x * blockDim.x + threadIdx.x;
    if (t >= NTOK) return;
#pragma unroll
    for (int k = 0; k < TOPK; k++) {
        int e = g_tok_e[2 * t + k];
        int pos = atomicAdd(&g_cursor[e], 1);
        int row = g_offset[e] + pos;
        g_perm[row] = t;
        g_gw[row] = g_tok_w[2 * t + k];
        g_rowof[2 * t + k] = row;
    }
}

// ---------------- K4: GEMM A  hid = silu(X@gateT) * (X@upT) ----------------
__global__ __launch_bounds__(256) void gemmA_kernel(const float* __restrict__ x,
                                                    const float* __restrict__ gate_w,
                                                    const float* __restrict__ up_w) {
    int f0 = blockIdx.x * TN;
    int row0 = blockIdx.y * TM;
    if (row0 >= g_offset[NEXP]) return;
    int e = 0;
    while (g_offset[e + 1] <= row0) e++;

    __shared__ float As[KB][TM];
    __shared__ float Bg[KB][TN];
    __shared__ float Bu[KB][TN];
    __shared__ int toks[TM];

    int tid = threadIdx.x;
    if (tid < TM) toks[tid] = g_perm[row0 + tid];
    __syncthreads();

    int r  = tid >> 2;           // 0..63
    int kq = (tid & 3) * 4;      // 0,4,8,12
    int ty = tid >> 4, tx = tid & 15;

    int tokr = toks[r];
    const float* aptr = x + (size_t)(tokr < 0 ? 0 : tokr) * HDIM;
    const float* gptr = gate_w + ((size_t)e * FDIM + f0 + r) * HDIM;
    const float* uptr = up_w   + ((size_t)e * FDIM + f0 + r) * HDIM;
    bool aval = (tokr >= 0);

    float accg[4][4], accu[4][4];
#pragma unroll
    for (int i = 0; i < 4; i++)
#pragma unroll
        for (int j = 0; j < 4; j++) { accg[i][j] = 0.f; accu[i][j] = 0.f; }

    float4 av = aval ? *(const float4*)(aptr + kq) : make_float4(0.f, 0.f, 0.f, 0.f);
    float4 gv = *(const float4*)(gptr + kq);
    float4 uv = *(const float4*)(uptr + kq);

    const int NCHUNK = HDIM / KB;
    for (int kc = 0; kc < NCHUNK; kc++) {
        As[kq + 0][r] = av.x; As[kq + 1][r] = av.y; As[kq + 2][r] = av.z; As[kq + 3][r] = av.w;
        Bg[kq + 0][r] = gv.x; Bg[kq + 1][r] = gv.y; Bg[kq + 2][r] = gv.z; Bg[kq + 3][r] = gv.w;
        Bu[kq + 0][r] = uv.x; Bu[kq + 1][r] = uv.y; Bu[kq + 2][r] = uv.z; Bu[kq + 3][r] = uv.w;
        __syncthreads();

        if (kc + 1 < NCHUNK) {
            int k0n = (kc + 1) * KB + kq;
            av = aval ? *(const float4*)(aptr + k0n) : make_float4(0.f, 0.f, 0.f, 0.f);
            gv = *(const float4*)(gptr + k0n);
            uv = *(const float4*)(uptr + k0n);
        }

#pragma unroll
        for (int k = 0; k < KB; k++) {
            float4 a  = *(const float4*)&As[k][ty * 4];
            float4 bg = *(const float4*)&Bg[k][tx * 4];
            float4 bu = *(const float4*)&Bu[k][tx * 4];
            float ar[4] = {a.x, a.y, a.z, a.w};
            float bgr[4] = {bg.x, bg.y, bg.z, bg.w};
            float bur[4] = {bu.x, bu.y, bu.z, bu.w};
#pragma unroll
            for (int i = 0; i < 4; i++)
#pragma unroll
                for (int j = 0; j < 4; j++) {
                    accg[i][j] += ar[i] * bgr[j];
                    accu[i][j] += ar[i] * bur[j];
                }
        }
        __syncthreads();
    }

#pragma unroll
    for (int i = 0; i < 4; i++) {
        int row = row0 + ty * 4 + i;
#pragma unroll
        for (int j = 0; j < 4; j++) {
            int f = f0 + tx * 4 + j;
            float g = accg[i][j];
            float hidv = (g / (1.f + expf(-g))) * accu[i][j];  // silu(g)*u
            g_hid[(size_t)row * FDIM + f] = hidv;
        }
    }
}

// ---------------- K5: GEMM B  contrib = gw * (hid @ downT) ----------------
__global__ __launch_bounds__(256) void gemmB_kernel(const float* __restrict__ down_w) {
    int h0 = blockIdx.x * TN;
    int row0 = blockIdx.y * TM;
    if (row0 >= g_offset[NEXP]) return;
    int e = 0;
    while (g_offset[e + 1] <= row0) e++;

    __shared__ float As[KB][TM];
    __shared__ float Bs[KB][TN];

    int tid = threadIdx.x;
    int r  = tid >> 2;
    int kq = (tid & 3) * 4;
    int ty = tid >> 4, tx = tid & 15;

    const float* aptr = g_hid + (size_t)(row0 + r) * FDIM;
    const float* bptr = down_w + ((size_t)e * HDIM + h0 + r) * FDIM;

    float acc[4][4];
#pragma unroll
    for (int i = 0; i < 4; i++)
#pragma unroll
        for (int j = 0; j < 4; j++) acc[i][j] = 0.f;

    float4 av = *(const float4*)(aptr + kq);
    float4 bv = *(const float4*)(bptr + kq);

    const int NCHUNK = FDIM / KB;
    for (int kc = 0; kc < NCHUNK; kc++) {
        As[kq + 0][r] = av.x; As[kq + 1][r] = av.y; As[kq + 2][r] = av.z; As[kq + 3][r] = av.w;
        Bs[kq + 0][r] = bv.x; Bs[kq + 1][r] = bv.y; Bs[kq + 2][r] = bv.z; Bs[kq + 3][r] = bv.w;
        __syncthreads();

        if (kc + 1 < NCHUNK) {
            int k0n = (kc + 1) * KB + kq;
            av = *(const float4*)(aptr + k0n);
            bv = *(const float4*)(bptr + k0n);
        }

#pragma unroll
        for (int k = 0; k < KB; k++) {
            float4 a = *(const float4*)&As[k][ty * 4];
            float4 b = *(const float4*)&Bs[k][tx * 4];
            float ar[4] = {a.x, a.y, a.z, a.w};
            float br[4] = {b.x, b.y, b.z, b.w};
#pragma unroll
            for (int i = 0; i < 4; i++)
#pragma unroll
                for (int j = 0; j < 4; j++) acc[i][j] += ar[i] * br[j];
        }
        __syncthreads();
    }

#pragma unroll
    for (int i = 0; i < 4; i++) {
        int row = row0 + ty * 4 + i;
        float w = g_gw[row];
#pragma unroll
        for (int j = 0; j < 4; j++) {
            int h = h0 + tx * 4 + j;
            g_contrib[(size_t)row * HDIM + h] = w * acc[i][j];
        }
    }
}

// ---------------- K6: combine (atomic-free, deterministic) ----------------
__global__ void combine_kernel(float* __restrict__ out) {
    int idx = blockIdx.x * blockDim.x + threadIdx.x;   // over NTOK * HDIM/4
    if (idx >= NTOK * (HDIM / 4)) return;
    int n = idx >> 8;                 // HDIM/4 = 256 float4 per token
    int hq = (idx & 255) * 4;
    int r0 = g_rowof[2 * n + 0];
    int r1 = g_rowof[2 * n + 1];
    float4 c0 = *(const float4*)&g_contrib[(size_t)r0 * HDIM + hq];
    float4 c1 = *(const float4*)&g_contrib[(size_t)r1 * HDIM + hq];
    float4 o;
    o.x = c0.x + c1.x; o.y = c0.y + c1.y; o.z = c0.z + c1.z; o.w = c0.w + c1.w;
    *(float4*)&out[(size_t)n * HDIM + hq] = o;
}

// ---------------- launch ----------------
extern "C" void kernel_launch(void* const* d_in, const int* in_sizes, int n_in,
                              void* d_out, int out_size) {
    const float* x       = (const float*)d_in[0];
    const float* rw      = (const float*)d_in[1];
    const float* gate_w  = (const float*)d_in[2];
    const float* up_w    = (const float*)d_in[3];
    const float* down_w  = (const float*)d_in[4];
    float* out = (float*)d_out;

    int write_lb = (out_size > NTOK * HDIM) ? 1 : 0;
    float* lb_ptr = out + (size_t)NTOK * HDIM;

    init_kernel<<<(PADDED_CAP + 255) / 256, 256>>>();
    router_kernel<<<NTOK / 4, 128>>>(x, rw);
    scan_kernel<<<1, 1>>>(lb_ptr, write_lb);
    place_kernel<<<NTOK / 256, 256>>>();

    dim3 gA(FDIM / TN, PADDED_CAP / TM);   // (16, 520)
    gemmA_kernel<<<gA, 256>>>(x, gate_w, up_w);
    dim3 gB(HDIM / TN, PADDED_CAP / TM);   // (16, 520)
    gemmB_kernel<<<gB, 256>>>(down_w);

    combine_kernel<<<(NTOK * (HDIM / 4) + 255) / 256, 256>>>(out);
}

// round 6
// speedup vs baseline: 3.8039x; 3.8039x over previous
#include <cuda_runtime.h>
#include <math.h>
#include <stdint.h>

#define NTOK 16384
#define HDIM 1024
#define NEXP 8
#define TOPK 2
#define FDIM 1024
#define BM 128
#define BN 128
#define BK 32
#define NCH 32                                 // 1024 / BK
#define RSTRIDE 36                             // smem row stride in floats (pad 32->36)
#define TILEB (BM * RSTRIDE * 4)               // 18432 B per operand tile
#define BUFB (2 * TILEB)                       // A+B per stage
#define SMEM_GEMM (2 * BUFB)                   // 73728 B dynamic smem
#define NASSIGN (NTOK * TOPK)
#define PADDED_CAP (NASSIGN + NEXP * BM)       // 33792
#define ROWTILES (PADDED_CAP / BM)             // 264
#define NWEIGHT (NEXP * FDIM * HDIM)

// ---- scratch (static, no allocs) ----
__device__ __align__(1024) float g_xr[(size_t)NTOK * HDIM];
__device__ __align__(1024) float g_gater[(size_t)NWEIGHT];
__device__ __align__(1024) float g_upr[(size_t)NWEIGHT];
__device__ __align__(1024) float g_downr[(size_t)NWEIGHT];
__device__ __align__(1024) float g_hidg[(size_t)PADDED_CAP * FDIM];
__device__ __align__(1024) float g_hidu[(size_t)PADDED_CAP * FDIM];
__device__ __align__(1024) float g_hid[(size_t)PADDED_CAP * FDIM];
__device__ __align__(1024) float g_contrib[(size_t)PADDED_CAP * HDIM];
__device__ int   g_perm[PADDED_CAP];
__device__ float g_gw[PADDED_CAP];
__device__ int   g_rowof[NASSIGN];
__device__ int   g_tok_e[NASSIGN];
__device__ float g_tok_w[NASSIGN];
__device__ int   g_count[NEXP];
__device__ int   g_cursor[NEXP];
__device__ float g_usage[NEXP];
__device__ int   g_offset[NEXP + 1];

// ---- helpers ----
__device__ __forceinline__ uint32_t smem_u32(const void* p) {
    uint32_t a;
    asm("{ .reg .u64 t; cvta.to.shared.u64 t, %1; cvt.u32.u64 %0, t; }" : "=r"(a) : "l"(p));
    return a;
}
__device__ __forceinline__ void cp16(uint32_t d, const void* s) {
    asm volatile("cp.async.cg.shared.global [%0], [%1], 16;" :: "r"(d), "l"(s) : "memory");
}
#define CP_COMMIT() asm volatile("cp.async.commit_group;" ::: "memory")
#define CP_WAIT1()  asm volatile("cp.async.wait_group 1;" ::: "memory")
#define CP_WAIT0()  asm volatile("cp.async.wait_group 0;" ::: "memory")

__device__ __forceinline__ float rna_tf32(float v) {
    uint32_t r;
    asm("cvt.rna.tf32.f32 %0, %1;" : "=r"(r) : "f"(v));
    return __uint_as_float(r);
}
#define MMA8(c, a0, a1, a2, a3, b0, b1) \
    asm volatile("mma.sync.aligned.m16n8k8.row.col.f32.tf32.tf32.f32 " \
        "{%0,%1,%2,%3},{%4,%5,%6,%7},{%8,%9},{%0,%1,%2,%3};" \
        : "+f"((c)[0]), "+f"((c)[1]), "+f"((c)[2]), "+f"((c)[3]) \
        : "r"(a0), "r"(a1), "r"(a2), "r"(a3), "r"(b0), "r"(b1))

// ---- rounding pass (RTN to tf32) ----
__global__ __launch_bounds__(256) void round_kernel(const float4* __restrict__ s, float4* __restrict__ d, int n4) {
    int st = gridDim.x * blockDim.x;
    for (int i = blockIdx.x * blockDim.x + threadIdx.x; i < n4; i += st) {
        float4 v = s[i];
        d[i] = make_float4(rna_tf32(v.x), rna_tf32(v.y), rna_tf32(v.z), rna_tf32(v.w));
    }
}

// ---- init ----
__global__ void init_kernel() {
    int i = blockIdx.x * blockDim.x + threadIdx.x;
    if (i < PADDED_CAP) g_perm[i] = -1;
    if (i < NEXP) { g_count[i] = 0; g_cursor[i] = 0; g_usage[i] = 0.f; }
}

// ---- router (exact fp32) ----
__global__ __launch_bounds__(128) void router_kernel(const float* __restrict__ x, const float* __restrict__ rw) {
    __shared__ float srw[NEXP * HDIM];
    __shared__ float sprob[NEXP];
    int tid = threadIdx.x;
    for (int i = tid; i < NEXP * HDIM; i += 128) srw[i] = rw[i];
    if (tid < NEXP) sprob[tid] = 0.f;
    __syncthreads();
    int warp = tid >> 5, lane = tid & 31;
    int t = blockIdx.x * 4 + warp;
    float acc[NEXP];
#pragma unroll
    for (int e = 0; e < NEXP; e++) acc[e] = 0.f;
    const float* xp = x + (size_t)t * HDIM;
    for (int j = lane; j < HDIM; j += 32) {
        float xv = xp[j];
#pragma unroll
        for (int e = 0; e < NEXP; e++) acc[e] += xv * srw[e * HDIM + j];
    }
#pragma unroll
    for (int e = 0; e < NEXP; e++)
#pragma unroll
        for (int o = 16; o; o >>= 1) acc[e] += __shfl_xor_sync(~0u, acc[e], o);
    if (lane == 0) {
        float mx = acc[0];
#pragma unroll
        for (int e = 1; e < NEXP; e++) mx = fmaxf(mx, acc[e]);
        float p[NEXP], s = 0.f;
#pragma unroll
        for (int e = 0; e < NEXP; e++) { p[e] = expf(acc[e] - mx); s += p[e]; }
        float inv = 1.f / s;
#pragma unroll
        for (int e = 0; e < NEXP; e++) p[e] *= inv;
        int e1 = 0;
#pragma unroll
        for (int e = 1; e < NEXP; e++) if (p[e] > p[e1]) e1 = e;
        int e2 = (e1 == 0) ? 1 : 0;
#pragma unroll
        for (int e = 0; e < NEXP; e++) if (e != e1 && p[e] > p[e2]) e2 = e;
        float ws = p[e1] + p[e2];
        g_tok_e[2 * t] = e1;     g_tok_w[2 * t] = p[e1] / ws;
        g_tok_e[2 * t + 1] = e2; g_tok_w[2 * t + 1] = p[e2] / ws;
        atomicAdd(&g_count[e1], 1);
        atomicAdd(&g_count[e2], 1);
#pragma unroll
        for (int e = 0; e < NEXP; e++) atomicAdd(&sprob[e], p[e]);
    }
    __syncthreads();
    if (tid < NEXP) atomicAdd(&g_usage[tid], sprob[tid]);
}

// ---- scan + lb ----
__global__ void scan_kernel(float* lb_out, int wlb) {
    int off = 0;
    for (int e = 0; e < NEXP; e++) {
        g_offset[e] = off;
        off += ((g_count[e] + BM - 1) / BM) * BM;
    }
    g_offset[NEXP] = off;
    if (wlb) {
        float s = 0.f;
        for (int e = 0; e < NEXP; e++) { float u = g_usage[e] / (float)NTOK; s += u * u; }
        *lb_out = 0.01f * (float)NEXP * s;
    }
}

// ---- placement ----
__global__ void place_kernel() {
    int t = blockIdx.x * blockDim.x + threadIdx.x;
    if (t >= NTOK) return;
#pragma unroll
    for (int k = 0; k < TOPK; k++) {
        int e = g_tok_e[2 * t + k];
        int pos = atomicAdd(&g_cursor[e], 1);
        int row = g_offset[e] + pos;
        g_perm[row] = t;
        g_gw[row] = g_tok_w[2 * t + k];
        g_rowof[2 * t + k] = row;
    }
}

// ==== GEMM core (mma.sync tf32, 128x128x32, 8 warps, warp 64x32) ====
// gather=1: A rows gathered via g_perm from g_xr; gather=0: A rows = asrc + row.
// scale=1: multiply output rows by g_gw[row] (GEMM B).
template <int GATHER, int SCALE>
__device__ __forceinline__ void gemm_body(const float* __restrict__ asrc,
                                          const float* __restrict__ bw,
                                          float* __restrict__ dst,
                                          int ldb_rows_base, int out_ld) {
    extern __shared__ char smem[];
    __shared__ int toks[BM];
    const int tid = threadIdx.x;
    const int row0 = blockIdx.y * BM;
    const int total = g_offset[NEXP];
    if (row0 >= total) return;
    const int n0 = blockIdx.x * BN;
    int e = 0;
    while (g_offset[e + 1] <= row0) e++;

    if (GATHER) {
        if (tid < BM) { int tk = g_perm[row0 + tid]; toks[tid] = tk < 0 ? 0 : tk; }
        __syncthreads();
    }
    const uint32_t sbase = smem_u32(smem);
    const float* bbase = bw + ((size_t)e * ldb_rows_base + n0) * 1024;

    // pipeline: issue chunk into buffer (kc&1)
    auto load_chunk = [&](int kc) {
        const int buf = kc & 1;
        const uint32_t sa = sbase + buf * BUFB;
        const uint32_t sb2 = sa + TILEB;
#pragma unroll
        for (int i = 0; i < 4; i++) {
            const int slot = tid + i * 256;
            const int row = slot >> 3, seg = slot & 7;
            const float* as = GATHER
                ? g_xr + (size_t)toks[row] * 1024 + kc * BK + seg * 4
                : asrc + (size_t)(row0 + row) * 1024 + kc * BK + seg * 4;
            cp16(sa + row * (RSTRIDE * 4) + seg * 16, as);
            cp16(sb2 + row * (RSTRIDE * 4) + seg * 16,
                 bbase + (size_t)row * 1024 + kc * BK + seg * 4);
        }
        CP_COMMIT();
    };

    const int wid = tid >> 5, lane = tid & 31;
    const int wm = wid & 1, wn = wid >> 1;
    const int g = lane >> 2, tg = lane & 3;

    float acc[4][4][4];
#pragma unroll
    for (int i = 0; i < 4; i++)
#pragma unroll
        for (int j = 0; j < 4; j++)
#pragma unroll
            for (int k = 0; k < 4; k++) acc[i][j][k] = 0.f;

    load_chunk(0);
    for (int kc = 0; kc < NCH; kc++) {
        if (kc + 1 < NCH) { load_chunk(kc + 1); CP_WAIT1(); }
        else              { CP_WAIT0(); }
        __syncthreads();
        const int buf = kc & 1;
        const uint32_t* As = (const uint32_t*)(smem + buf * BUFB);
        const uint32_t* Bs = (const uint32_t*)(smem + buf * BUFB + TILEB);
#pragma unroll
        for (int ks = 0; ks < 4; ks++) {
            const int kb = ks * 8;
            uint32_t af[4][4], bf[4][2];
#pragma unroll
            for (int mt = 0; mt < 4; mt++) {
                const int ar = wm * 64 + mt * 16 + g;
                af[mt][0] = As[ar * RSTRIDE + kb + tg];
                af[mt][1] = As[(ar + 8) * RSTRIDE + kb + tg];
                af[mt][2] = As[ar * RSTRIDE + kb + tg + 4];
                af[mt][3] = As[(ar + 8) * RSTRIDE + kb + tg + 4];
            }
#pragma unroll
            for (int nt = 0; nt < 4; nt++) {
                const int br = wn * 32 + nt * 8 + g;
                bf[nt][0] = Bs[br * RSTRIDE + kb + tg];
                bf[nt][1] = Bs[br * RSTRIDE + kb + tg + 4];
            }
#pragma unroll
            for (int mt = 0; mt < 4; mt++)
#pragma unroll
                for (int nt = 0; nt < 4; nt++)
                    MMA8(acc[mt][nt], af[mt][0], af[mt][1], af[mt][2], af[mt][3],
                         bf[nt][0], bf[nt][1]);
        }
        __syncthreads();
    }

    // epilogue
#pragma unroll
    for (int mt = 0; mt < 4; mt++) {
        const int r0 = row0 + wm * 64 + mt * 16 + g;
        const int r8 = r0 + 8;
        float w0 = 1.f, w8 = 1.f;
        if (SCALE) { w0 = g_gw[r0]; w8 = g_gw[r8]; }
#pragma unroll
        for (int nt = 0; nt < 4; nt++) {
            const int c = n0 + wn * 32 + nt * 8 + 2 * tg;
            float2 v0 = make_float2(acc[mt][nt][0] * w0, acc[mt][nt][1] * w0);
            float2 v1 = make_float2(acc[mt][nt][2] * w8, acc[mt][nt][3] * w8);
            *(float2*)(dst + (size_t)r0 * out_ld + c) = v0;
            *(float2*)(dst + (size_t)r8 * out_ld + c) = v1;
        }
    }
}

__global__ __launch_bounds__(256, 2) void gemmA_kernel(const float* __restrict__ bw,
                                                       float* __restrict__ dst) {
    gemm_body<1, 0>(nullptr, bw, dst, FDIM, FDIM);
}
__global__ __launch_bounds__(256, 2) void gemmB_kernel() {
    gemm_body<0, 1>(g_hid, g_downr, g_contrib, HDIM, HDIM);
}

// ---- SwiGLU elementwise: hid = rna( silu(g) * u ) ----
__global__ __launch_bounds__(256) void silu_kernel() {
    int idx = blockIdx.x * blockDim.x + threadIdx.x;
    if (idx >= PADDED_CAP * (FDIM / 4)) return;
    int row = idx >> 8;
    if (row >= g_offset[NEXP]) return;
    float4 gv = *(const float4*)&g_hidg[(size_t)idx * 4];
    float4 uv = *(const float4*)&g_hidu[(size_t)idx * 4];
    float4 o;
    o.x = rna_tf32(__fdividef(gv.x, 1.f + __expf(-gv.x)) * uv.x);
    o.y = rna_tf32(__fdividef(gv.y, 1.f + __expf(-gv.y)) * uv.y);
    o.z = rna_tf32(__fdividef(gv.z, 1.f + __expf(-gv.z)) * uv.z);
    o.w = rna_tf32(__fdividef(gv.w, 1.f + __expf(-gv.w)) * uv.w);
    *(float4*)&g_hid[(size_t)idx * 4] = o;
}

// ---- combine (deterministic) ----
__global__ void combine_kernel(float* __restrict__ out) {
    int idx = blockIdx.x * blockDim.x + threadIdx.x;
    if (idx >= NTOK * (HDIM / 4)) return;
    int n = idx >> 8;
    int hq = (idx & 255) * 4;
    int r0 = g_rowof[2 * n], r1 = g_rowof[2 * n + 1];
    float4 a = *(const float4*)&g_contrib[(size_t)r0 * HDIM + hq];
    float4 b = *(const float4*)&g_contrib[(size_t)r1 * HDIM + hq];
    *(float4*)&out[(size_t)n * HDIM + hq] =
        make_float4(a.x + b.x, a.y + b.y, a.z + b.z, a.w + b.w);
}

// ---- launch ----
extern "C" void kernel_launch(void* const* d_in, const int* in_sizes, int n_in,
                              void* d_out, int out_size) {
    const float* x  = (const float*)d_in[0];
    const float* rw = (const float*)d_in[1];
    const float* gw = (const float*)d_in[2];
    const float* uw = (const float*)d_in[3];
    const float* dw = (const float*)d_in[4];
    float* out = (float*)d_out;
    int wlb = (out_size > NTOK * HDIM) ? 1 : 0;
    float* lb_ptr = out + (size_t)NTOK * HDIM;

    cudaFuncSetAttribute(gemmA_kernel, cudaFuncAttributeMaxDynamicSharedMemorySize, SMEM_GEMM);
    cudaFuncSetAttribute(gemmB_kernel, cudaFuncAttributeMaxDynamicSharedMemorySize, SMEM_GEMM);

    float* xr;  cudaGetSymbolAddress((void**)&xr, g_xr);
    float* gr;  cudaGetSymbolAddress((void**)&gr, g_gater);
    float* ur;  cudaGetSymbolAddress((void**)&ur, g_upr);
    float* dr;  cudaGetSymbolAddress((void**)&dr, g_downr);
    float* hg;  cudaGetSymbolAddress((void**)&hg, g_hidg);
    float* hu;  cudaGetSymbolAddress((void**)&hu, g_hidu);

    round_kernel<<<1024, 256>>>((const float4*)x,  (float4*)xr, NTOK * HDIM / 4);
    round_kernel<<<1024, 256>>>((const float4*)gw, (float4*)gr, NWEIGHT / 4);
    round_kernel<<<1024, 256>>>((const float4*)uw, (float4*)ur, NWEIGHT / 4);
    round_kernel<<<1024, 256>>>((const float4*)dw, (float4*)dr, NWEIGHT / 4);

    init_kernel<<<(PADDED_CAP + 255) / 256, 256>>>();
    router_kernel<<<NTOK / 4, 128>>>(x, rw);
    scan_kernel<<<1, 1>>>(lb_ptr, wlb);
    place_kernel<<<NTOK / 256, 256>>>();

    dim3 gA(FDIM / BN, ROWTILES);                    // (8, 264)
    gemmA_kernel<<<gA, 256, SMEM_GEMM>>>(gr, hg);
    gemmA_kernel<<<gA, 256, SMEM_GEMM>>>(ur, hu);
    silu_kernel<<<(PADDED_CAP * (FDIM / 4) + 255) / 256, 256>>>();
    dim3 gB(HDIM / BN, ROWTILES);                    // (8, 264)
    gemmB_kernel<<<gB, 256, SMEM_GEMM>>>();

    combine_kernel<<<(NTOK * (HDIM / 4) + 255) / 256, 256>>>(out);
}

// round 7
// speedup vs baseline: 3.9206x; 1.0307x over previous
#include <cuda_runtime.h>
#include <math.h>
#include <stdint.h>

#define NTOK 16384
#define HDIM 1024
#define NEXP 8
#define TOPK 2
#define FDIM 1024
#define BM 128
#define BN 128
#define BK 32
#define NCH 32
#define RSTRIDE 36
#define TILEB (BM * RSTRIDE * 4)               // 18432 B
#define BUFB (2 * TILEB)
#define SMEM_GEMM (2 * BUFB)                   // 73728 B
#define NASSIGN (NTOK * TOPK)
#define PADDED_CAP (NASSIGN + NEXP * BM)       // 33792
#define ROWTILES (PADDED_CAP / BM)             // 264
#define NWEIGHT (NEXP * FDIM * HDIM)

// ---- scratch (static, no allocs) ----
__device__ __align__(1024) float g_xr[(size_t)NTOK * HDIM];
__device__ __align__(1024) float g_gater[(size_t)NWEIGHT];
__device__ __align__(1024) float g_upr[(size_t)NWEIGHT];
__device__ __align__(1024) float g_downr[(size_t)NWEIGHT];
__device__ __align__(1024) float g_hid[(size_t)PADDED_CAP * FDIM];
__device__ __align__(1024) float g_contrib[(size_t)PADDED_CAP * HDIM];
__device__ int   g_perm[PADDED_CAP];
__device__ float g_gw[PADDED_CAP];
__device__ int   g_rowof[NASSIGN];
__device__ int   g_tok_e[NASSIGN];
__device__ float g_tok_w[NASSIGN];
__device__ int   g_count[NEXP];
__device__ int   g_cursor[NEXP];
__device__ float g_usage[NEXP];
__device__ int   g_offset[NEXP + 1];

// ---- helpers ----
__device__ __forceinline__ void cp16(uint32_t d, const void* s) {
    asm volatile("cp.async.cg.shared.global [%0], [%1], 16;" :: "r"(d), "l"(s) : "memory");
}
__device__ __forceinline__ uint32_t smem_u32(const void* p) {
    uint32_t a;
    asm("{ .reg .u64 t; cvta.to.shared.u64 t, %1; cvt.u32.u64 %0, t; }" : "=r"(a) : "l"(p));
    return a;
}
#define CP_COMMIT() asm volatile("cp.async.commit_group;" ::: "memory")
#define CP_WAIT1()  asm volatile("cp.async.wait_group 1;" ::: "memory")
#define CP_WAIT0()  asm volatile("cp.async.wait_group 0;" ::: "memory")

__device__ __forceinline__ float rna_tf32(float v) {
    uint32_t r;
    asm("cvt.rna.tf32.f32 %0, %1;" : "=r"(r) : "f"(v));
    return __uint_as_float(r);
}
#define MMA8(c, a0, a1, a2, a3, b0, b1) \
    asm volatile("mma.sync.aligned.m16n8k8.row.col.f32.tf32.tf32.f32 " \
        "{%0,%1,%2,%3},{%4,%5,%6,%7},{%8,%9},{%0,%1,%2,%3};" \
        : "+f"((c)[0]), "+f"((c)[1]), "+f"((c)[2]), "+f"((c)[3]) \
        : "r"(a0), "r"(a1), "r"(a2), "r"(a3), "r"(b0), "r"(b1))

// ---- rounding (RTN -> tf32) ----
__global__ __launch_bounds__(256) void round_kernel(const float4* __restrict__ s, float4* __restrict__ d, int n4) {
    int st = gridDim.x * blockDim.x;
    for (int i = blockIdx.x * blockDim.x + threadIdx.x; i < n4; i += st) {
        float4 v = s[i];
        d[i] = make_float4(rna_tf32(v.x), rna_tf32(v.y), rna_tf32(v.z), rna_tf32(v.w));
    }
}

// ---- init ----
__global__ void init_kernel() {
    int i = blockIdx.x * blockDim.x + threadIdx.x;
    if (i < PADDED_CAP) g_perm[i] = -1;
    if (i < NEXP) { g_count[i] = 0; g_cursor[i] = 0; g_usage[i] = 0.f; }
}

// ---- router (exact fp32) ----
__global__ __launch_bounds__(128) void router_kernel(const float* __restrict__ x, const float* __restrict__ rw) {
    __shared__ float srw[NEXP * HDIM];
    __shared__ float sprob[NEXP];
    int tid = threadIdx.x;
    for (int i = tid; i < NEXP * HDIM; i += 128) srw[i] = rw[i];
    if (tid < NEXP) sprob[tid] = 0.f;
    __syncthreads();
    int warp = tid >> 5, lane = tid & 31;
    int t = blockIdx.x * 4 + warp;
    float acc[NEXP];
#pragma unroll
    for (int e = 0; e < NEXP; e++) acc[e] = 0.f;
    const float* xp = x + (size_t)t * HDIM;
    for (int j = lane; j < HDIM; j += 32) {
        float xv = xp[j];
#pragma unroll
        for (int e = 0; e < NEXP; e++) acc[e] += xv * srw[e * HDIM + j];
    }
#pragma unroll
    for (int e = 0; e < NEXP; e++)
#pragma unroll
        for (int o = 16; o; o >>= 1) acc[e] += __shfl_xor_sync(~0u, acc[e], o);
    if (lane == 0) {
        float mx = acc[0];
#pragma unroll
        for (int e = 1; e < NEXP; e++) mx = fmaxf(mx, acc[e]);
        float p[NEXP], s = 0.f;
#pragma unroll
        for (int e = 0; e < NEXP; e++) { p[e] = expf(acc[e] - mx); s += p[e]; }
        float inv = 1.f / s;
#pragma unroll
        for (int e = 0; e < NEXP; e++) p[e] *= inv;
        int e1 = 0;
#pragma unroll
        for (int e = 1; e < NEXP; e++) if (p[e] > p[e1]) e1 = e;
        int e2 = (e1 == 0) ? 1 : 0;
#pragma unroll
        for (int e = 0; e < NEXP; e++) if (e != e1 && p[e] > p[e2]) e2 = e;
        float ws = p[e1] + p[e2];
        g_tok_e[2 * t] = e1;     g_tok_w[2 * t] = p[e1] / ws;
        g_tok_e[2 * t + 1] = e2; g_tok_w[2 * t + 1] = p[e2] / ws;
        atomicAdd(&g_count[e1], 1);
        atomicAdd(&g_count[e2], 1);
#pragma unroll
        for (int e = 0; e < NEXP; e++) atomicAdd(&sprob[e], p[e]);
    }
    __syncthreads();
    if (tid < NEXP) atomicAdd(&g_usage[tid], sprob[tid]);
}

// ---- scan + lb ----
__global__ void scan_kernel(float* lb_out, int wlb) {
    int off = 0;
    for (int e = 0; e < NEXP; e++) {
        g_offset[e] = off;
        off += ((g_count[e] + BM - 1) / BM) * BM;
    }
    g_offset[NEXP] = off;
    if (wlb) {
        float s = 0.f;
        for (int e = 0; e < NEXP; e++) { float u = g_usage[e] / (float)NTOK; s += u * u; }
        *lb_out = 0.01f * (float)NEXP * s;
    }
}

// ---- placement ----
__global__ void place_kernel() {
    int t = blockIdx.x * blockDim.x + threadIdx.x;
    if (t >= NTOK) return;
#pragma unroll
    for (int k = 0; k < TOPK; k++) {
        int e = g_tok_e[2 * t + k];
        int pos = atomicAdd(&g_cursor[e], 1);
        int row = g_offset[e] + pos;
        g_perm[row] = t;
        g_gw[row] = g_tok_w[2 * t + k];
        g_rowof[2 * t + k] = row;
    }
}

// ==== Fused GEMM A: hid = rna(silu(X@gT) * (X@uT)), CTA 128rows x 64f ====
// B smem tile: rows 0-63 = gate[f0..f0+64), rows 64-127 = up[f0..f0+64).
__global__ __launch_bounds__(256, 2) void gemmA_fused() {
    extern __shared__ char smem[];
    __shared__ int toks[BM];
    const int tid = threadIdx.x;
    const int row0 = blockIdx.y * BM;
    if (row0 >= g_offset[NEXP]) return;
    const int f0 = blockIdx.x * 64;
    int e = 0;
    while (g_offset[e + 1] <= row0) e++;

    if (tid < BM) { int tk = g_perm[row0 + tid]; toks[tid] = tk < 0 ? 0 : tk; }
    __syncthreads();

    const uint32_t sbase = smem_u32(smem);
    const float* bg = g_gater + ((size_t)e * FDIM + f0) * 1024;
    const float* bu = g_upr   + ((size_t)e * FDIM + f0) * 1024;

    auto load_chunk = [&](int kc) {
        const int buf = kc & 1;
        const uint32_t sa = sbase + buf * BUFB;
        const uint32_t sb2 = sa + TILEB;
#pragma unroll
        for (int i = 0; i < 4; i++) {
            const int slot = tid + i * 256;
            const int row = slot >> 3, seg = slot & 7;
            cp16(sa + row * (RSTRIDE * 4) + seg * 16,
                 g_xr + (size_t)toks[row] * 1024 + kc * BK + seg * 4);
            const float* bs = (row < 64)
                ? bg + (size_t)row * 1024 + kc * BK + seg * 4
                : bu + (size_t)(row - 64) * 1024 + kc * BK + seg * 4;
            cp16(sb2 + row * (RSTRIDE * 4) + seg * 16, bs);
        }
        CP_COMMIT();
    };

    const int wid = tid >> 5, lane = tid & 31;
    const int wm = wid & 1, wn = wid >> 1;        // wm: row half, wn: 16-col group
    const int g = lane >> 2, tg = lane & 3;

    float accg[4][2][4], accu[4][2][4];
#pragma unroll
    for (int i = 0; i < 4; i++)
#pragma unroll
        for (int j = 0; j < 2; j++)
#pragma unroll
            for (int k = 0; k < 4; k++) { accg[i][j][k] = 0.f; accu[i][j][k] = 0.f; }

    load_chunk(0);
    for (int kc = 0; kc < NCH; kc++) {
        if (kc + 1 < NCH) { load_chunk(kc + 1); CP_WAIT1(); }
        else              { CP_WAIT0(); }
        __syncthreads();
        const int buf = kc & 1;
        const uint32_t* As = (const uint32_t*)(smem + buf * BUFB);
        const uint32_t* Bs = (const uint32_t*)(smem + buf * BUFB + TILEB);
#pragma unroll
        for (int ks = 0; ks < 4; ks++) {
            const int kb = ks * 8;
            uint32_t af[4][4], bfg[2][2], bfu[2][2];
#pragma unroll
            for (int mt = 0; mt < 4; mt++) {
                const int ar = wm * 64 + mt * 16 + g;
                af[mt][0] = As[ar * RSTRIDE + kb + tg];
                af[mt][1] = As[(ar + 8) * RSTRIDE + kb + tg];
                af[mt][2] = As[ar * RSTRIDE + kb + tg + 4];
                af[mt][3] = As[(ar + 8) * RSTRIDE + kb + tg + 4];
            }
#pragma unroll
            for (int nt = 0; nt < 2; nt++) {
                const int brg = wn * 16 + nt * 8 + g;
                bfg[nt][0] = Bs[brg * RSTRIDE + kb + tg];
                bfg[nt][1] = Bs[brg * RSTRIDE + kb + tg + 4];
                const int bru = 64 + brg;
                bfu[nt][0] = Bs[bru * RSTRIDE + kb + tg];
                bfu[nt][1] = Bs[bru * RSTRIDE + kb + tg + 4];
            }
#pragma unroll
            for (int mt = 0; mt < 4; mt++)
#pragma unroll
                for (int nt = 0; nt < 2; nt++) {
                    MMA8(accg[mt][nt], af[mt][0], af[mt][1], af[mt][2], af[mt][3],
                         bfg[nt][0], bfg[nt][1]);
                    MMA8(accu[mt][nt], af[mt][0], af[mt][1], af[mt][2], af[mt][3],
                         bfu[nt][0], bfu[nt][1]);
                }
        }
        __syncthreads();
    }

    // epilogue: SwiGLU + tf32 re-round, write hid
#pragma unroll
    for (int mt = 0; mt < 4; mt++) {
        const int r0 = row0 + wm * 64 + mt * 16 + g;
        const int r8 = r0 + 8;
#pragma unroll
        for (int nt = 0; nt < 2; nt++) {
            const int c = f0 + wn * 16 + nt * 8 + 2 * tg;
            float h0 = rna_tf32(__fdividef(accg[mt][nt][0], 1.f + __expf(-accg[mt][nt][0])) * accu[mt][nt][0]);
            float h1 = rna_tf32(__fdividef(accg[mt][nt][1], 1.f + __expf(-accg[mt][nt][1])) * accu[mt][nt][1]);
            float h2 = rna_tf32(__fdividef(accg[mt][nt][2], 1.f + __expf(-accg[mt][nt][2])) * accu[mt][nt][2]);
            float h3 = rna_tf32(__fdividef(accg[mt][nt][3], 1.f + __expf(-accg[mt][nt][3])) * accu[mt][nt][3]);
            *(float2*)(g_hid + (size_t)r0 * FDIM + c) = make_float2(h0, h1);
            *(float2*)(g_hid + (size_t)r8 * FDIM + c) = make_float2(h2, h3);
        }
    }
}

// ==== GEMM B: contrib = gw * (hid @ downT), CTA 128x128 ====
__global__ __launch_bounds__(256, 2) void gemmB_kernel() {
    extern __shared__ char smem[];
    const int tid = threadIdx.x;
    const int row0 = blockIdx.y * BM;
    if (row0 >= g_offset[NEXP]) return;
    const int n0 = blockIdx.x * BN;
    int e = 0;
    while (g_offset[e + 1] <= row0) e++;

    const uint32_t sbase = smem_u32(smem);
    const float* bbase = g_downr + ((size_t)e * HDIM + n0) * 1024;

    auto load_chunk = [&](int kc) {
        const int buf = kc & 1;
        const uint32_t sa = sbase + buf * BUFB;
        const uint32_t sb2 = sa + TILEB;
#pragma unroll
        for (int i = 0; i < 4; i++) {
            const int slot = tid + i * 256;
            const int row = slot >> 3, seg = slot & 7;
            cp16(sa + row * (RSTRIDE * 4) + seg * 16,
                 g_hid + (size_t)(row0 + row) * 1024 + kc * BK + seg * 4);
            cp16(sb2 + row * (RSTRIDE * 4) + seg * 16,
                 bbase + (size_t)row * 1024 + kc * BK + seg * 4);
        }
        CP_COMMIT();
    };

    const int wid = tid >> 5, lane = tid & 31;
    const int wm = wid & 1, wn = wid >> 1;
    const int g = lane >> 2, tg = lane & 3;

    float acc[4][4][4];
#pragma unroll
    for (int i = 0; i < 4; i++)
#pragma unroll
        for (int j = 0; j < 4; j++)
#pragma unroll
            for (int k = 0; k < 4; k++) acc[i][j][k] = 0.f;

    load_chunk(0);
    for (int kc = 0; kc < NCH; kc++) {
        if (kc + 1 < NCH) { load_chunk(kc + 1); CP_WAIT1(); }
        else              { CP_WAIT0(); }
        __syncthreads();
        const int buf = kc & 1;
        const uint32_t* As = (const uint32_t*)(smem + buf * BUFB);
        const uint32_t* Bs = (const uint32_t*)(smem + buf * BUFB + TILEB);
#pragma unroll
        for (int ks = 0; ks < 4; ks++) {
            const int kb = ks * 8;
            uint32_t af[4][4], bf[4][2];
#pragma unroll
            for (int mt = 0; mt < 4; mt++) {
                const int ar = wm * 64 + mt * 16 + g;
                af[mt][0] = As[ar * RSTRIDE + kb + tg];
                af[mt][1] = As[(ar + 8) * RSTRIDE + kb + tg];
                af[mt][2] = As[ar * RSTRIDE + kb + tg + 4];
                af[mt][3] = As[(ar + 8) * RSTRIDE + kb + tg + 4];
            }
#pragma unroll
            for (int nt = 0; nt < 4; nt++) {
                const int br = wn * 32 + nt * 8 + g;
                bf[nt][0] = Bs[br * RSTRIDE + kb + tg];
                bf[nt][1] = Bs[br * RSTRIDE + kb + tg + 4];
            }
#pragma unroll
            for (int mt = 0; mt < 4; mt++)
#pragma unroll
                for (int nt = 0; nt < 4; nt++)
                    MMA8(acc[mt][nt], af[mt][0], af[mt][1], af[mt][2], af[mt][3],
                         bf[nt][0], bf[nt][1]);
        }
        __syncthreads();
    }

#pragma unroll
    for (int mt = 0; mt < 4; mt++) {
        const int r0 = row0 + wm * 64 + mt * 16 + g;
        const int r8 = r0 + 8;
        const float w0 = g_gw[r0], w8 = g_gw[r8];
#pragma unroll
        for (int nt = 0; nt < 4; nt++) {
            const int c = n0 + wn * 32 + nt * 8 + 2 * tg;
            *(float2*)(g_contrib + (size_t)r0 * HDIM + c) =
                make_float2(acc[mt][nt][0] * w0, acc[mt][nt][1] * w0);
            *(float2*)(g_contrib + (size_t)r8 * HDIM + c) =
                make_float2(acc[mt][nt][2] * w8, acc[mt][nt][3] * w8);
        }
    }
}

// ---- combine (deterministic) ----
__global__ void combine_kernel(float* __restrict__ out) {
    int idx = blockIdx.x * blockDim.x + threadIdx.x;
    if (idx >= NTOK * (HDIM / 4)) return;
    int n = idx >> 8;
    int hq = (idx & 255) * 4;
    int r0 = g_rowof[2 * n], r1 = g_rowof[2 * n + 1];
    float4 a = *(const float4*)&g_contrib[(size_t)r0 * HDIM + hq];
    float4 b = *(const float4*)&g_contrib[(size_t)r1 * HDIM + hq];
    *(float4*)&out[(size_t)n * HDIM + hq] =
        make_float4(a.x + b.x, a.y + b.y, a.z + b.z, a.w + b.w);
}

// ---- launch ----
extern "C" void kernel_launch(void* const* d_in, const int* in_sizes, int n_in,
                              void* d_out, int out_size) {
    const float* x  = (const float*)d_in[0];
    const float* rw = (const float*)d_in[1];
    const float* gw = (const float*)d_in[2];
    const float* uw = (const float*)d_in[3];
    const float* dw = (const float*)d_in[4];
    float* out = (float*)d_out;
    int wlb = (out_size > NTOK * HDIM) ? 1 : 0;
    float* lb_ptr = out + (size_t)NTOK * HDIM;

    cudaFuncSetAttribute(gemmA_fused, cudaFuncAttributeMaxDynamicSharedMemorySize, SMEM_GEMM);
    cudaFuncSetAttribute(gemmB_kernel, cudaFuncAttributeMaxDynamicSharedMemorySize, SMEM_GEMM);

    float* xr;  cudaGetSymbolAddress((void**)&xr, g_xr);
    float* gr;  cudaGetSymbolAddress((void**)&gr, g_gater);
    float* ur;  cudaGetSymbolAddress((void**)&ur, g_upr);
    float* dr;  cudaGetSymbolAddress((void**)&dr, g_downr);

    round_kernel<<<1024, 256>>>((const float4*)x,  (float4*)xr, NTOK * HDIM / 4);
    round_kernel<<<1024, 256>>>((const float4*)gw, (float4*)gr, NWEIGHT / 4);
    round_kernel<<<1024, 256>>>((const float4*)uw, (float4*)ur, NWEIGHT / 4);
    round_kernel<<<1024, 256>>>((const float4*)dw, (float4*)dr, NWEIGHT / 4);

    init_kernel<<<(PADDED_CAP + 255) / 256, 256>>>();
    router_kernel<<<NTOK / 4, 128>>>(x, rw);
    scan_kernel<<<1, 1>>>(lb_ptr, wlb);
    place_kernel<<<NTOK / 256, 256>>>();

    dim3 gA(FDIM / 64, ROWTILES);                    // (16, 264)
    gemmA_fused<<<gA, 256, SMEM_GEMM>>>();
    dim3 gB(HDIM / BN, ROWTILES);                    // (8, 264)
    gemmB_kernel<<<gB, 256, SMEM_GEMM>>>();

    combine_kernel<<<(NTOK * (HDIM / 4) + 255) / 256, 256>>>(out);
}

// round 8
// speedup vs baseline: 4.4161x; 1.1264x over previous
#include <cuda_runtime.h>
#include <math.h>
#include <stdint.h>

#define NTOK 16384
#define HDIM 1024
#define NEXP 8
#define TOPK 2
#define FDIM 1024
#define BM 128
#define BK 32
#define NCH 32
#define RSTRIDE 36
#define TILEB (BM * RSTRIDE * 4)               // 18432 B
#define BUFB (2 * TILEB)
#define SMEM_GEMM (2 * BUFB)                   // 73728 B
#define NASSIGN (NTOK * TOPK)
#define PADDED_CAP (NASSIGN + NEXP * BM)       // 33792
#define ROWTILES (PADDED_CAP / BM)             // 264
#define NWEIGHT (NEXP * FDIM * HDIM)

// ---- scratch (static, no allocs) ----
__device__ __align__(1024) float g_xr[(size_t)NTOK * HDIM];
__device__ __align__(1024) float g_gater[(size_t)NWEIGHT];
__device__ __align__(1024) float g_upr[(size_t)NWEIGHT];
__device__ __align__(1024) float g_downr[(size_t)NWEIGHT];
__device__ __align__(1024) float g_hid[(size_t)PADDED_CAP * FDIM];
__device__ __align__(1024) float g_contrib[(size_t)PADDED_CAP * HDIM];
__device__ int   g_perm[PADDED_CAP];
__device__ float g_gw[PADDED_CAP];
__device__ int   g_rowof[NASSIGN];
__device__ int   g_tok_e[NASSIGN];
__device__ float g_tok_w[NASSIGN];
__device__ int   g_count[NEXP];
__device__ int   g_cursor[NEXP];
__device__ float g_usage[NEXP];
__device__ int   g_offset[NEXP + 1];

// ---- helpers ----
__device__ __forceinline__ void cp16(uint32_t d, const void* s) {
    asm volatile("cp.async.cg.shared.global [%0], [%1], 16;" :: "r"(d), "l"(s) : "memory");
}
__device__ __forceinline__ uint32_t smem_u32(const void* p) {
    uint32_t a;
    asm("{ .reg .u64 t; cvta.to.shared.u64 t, %1; cvt.u32.u64 %0, t; }" : "=r"(a) : "l"(p));
    return a;
}
#define CP_COMMIT() asm volatile("cp.async.commit_group;" ::: "memory")
#define CP_WAIT1()  asm volatile("cp.async.wait_group 1;" ::: "memory")
#define CP_WAIT0()  asm volatile("cp.async.wait_group 0;" ::: "memory")

__device__ __forceinline__ float rna_tf32(float v) {
    uint32_t r;
    asm("cvt.rna.tf32.f32 %0, %1;" : "=r"(r) : "f"(v));
    return __uint_as_float(r);
}
#define MMA8(c, a0, a1, a2, a3, b0, b1) \
    asm volatile("mma.sync.aligned.m16n8k8.row.col.f32.tf32.tf32.f32 " \
        "{%0,%1,%2,%3},{%4,%5,%6,%7},{%8,%9},{%0,%1,%2,%3};" \
        : "+f"((c)[0]), "+f"((c)[1]), "+f"((c)[2]), "+f"((c)[3]) \
        : "r"(a0), "r"(a1), "r"(a2), "r"(a3), "r"(b0), "r"(b1))

// ---- rounding (RTN -> tf32) ----
__global__ __launch_bounds__(256) void round_kernel(const float4* __restrict__ s, float4* __restrict__ d, int n4) {
    int st = gridDim.x * blockDim.x;
    for (int i = blockIdx.x * blockDim.x + threadIdx.x; i < n4; i += st) {
        float4 v = s[i];
        d[i] = make_float4(rna_tf32(v.x), rna_tf32(v.y), rna_tf32(v.z), rna_tf32(v.w));
    }
}

// ---- init ----
__global__ void init_kernel() {
    int i = blockIdx.x * blockDim.x + threadIdx.x;
    if (i < PADDED_CAP) g_perm[i] = -1;
    if (i < NEXP) { g_count[i] = 0; g_cursor[i] = 0; g_usage[i] = 0.f; }
}

// ---- router (exact fp32) ----
__global__ __launch_bounds__(128) void router_kernel(const float* __restrict__ x, const float* __restrict__ rw) {
    __shared__ float srw[NEXP * HDIM];
    __shared__ float sprob[NEXP];
    int tid = threadIdx.x;
    for (int i = tid; i < NEXP * HDIM; i += 128) srw[i] = rw[i];
    if (tid < NEXP) sprob[tid] = 0.f;
    __syncthreads();
    int warp = tid >> 5, lane = tid & 31;
    int t = blockIdx.x * 4 + warp;
    float acc[NEXP];
#pragma unroll
    for (int e = 0; e < NEXP; e++) acc[e] = 0.f;
    const float* xp = x + (size_t)t * HDIM;
    for (int j = lane; j < HDIM; j += 32) {
        float xv = xp[j];
#pragma unroll
        for (int e = 0; e < NEXP; e++) acc[e] += xv * srw[e * HDIM + j];
    }
#pragma unroll
    for (int e = 0; e < NEXP; e++)
#pragma unroll
        for (int o = 16; o; o >>= 1) acc[e] += __shfl_xor_sync(~0u, acc[e], o);
    if (lane == 0) {
        float mx = acc[0];
#pragma unroll
        for (int e = 1; e < NEXP; e++) mx = fmaxf(mx, acc[e]);
        float p[NEXP], s = 0.f;
#pragma unroll
        for (int e = 0; e < NEXP; e++) { p[e] = expf(acc[e] - mx); s += p[e]; }
        float inv = 1.f / s;
#pragma unroll
        for (int e = 0; e < NEXP; e++) p[e] *= inv;
        int e1 = 0;
#pragma unroll
        for (int e = 1; e < NEXP; e++) if (p[e] > p[e1]) e1 = e;
        int e2 = (e1 == 0) ? 1 : 0;
#pragma unroll
        for (int e = 0; e < NEXP; e++) if (e != e1 && p[e] > p[e2]) e2 = e;
        float ws = p[e1] + p[e2];
        g_tok_e[2 * t] = e1;     g_tok_w[2 * t] = p[e1] / ws;
        g_tok_e[2 * t + 1] = e2; g_tok_w[2 * t + 1] = p[e2] / ws;
        atomicAdd(&g_count[e1], 1);
        atomicAdd(&g_count[e2], 1);
#pragma unroll
        for (int e = 0; e < NEXP; e++) atomicAdd(&sprob[e], p[e]);
    }
    __syncthreads();
    if (tid < NEXP) atomicAdd(&g_usage[tid], sprob[tid]);
}

// ---- scan + lb ----
__global__ void scan_kernel(float* lb_out, int wlb) {
    int off = 0;
    for (int e = 0; e < NEXP; e++) {
        g_offset[e] = off;
        off += ((g_count[e] + BM - 1) / BM) * BM;
    }
    g_offset[NEXP] = off;
    if (wlb) {
        float s = 0.f;
        for (int e = 0; e < NEXP; e++) { float u = g_usage[e] / (float)NTOK; s += u * u; }
        *lb_out = 0.01f * (float)NEXP * s;
    }
}

// ---- placement ----
__global__ void place_kernel() {
    int t = blockIdx.x * blockDim.x + threadIdx.x;
    if (t >= NTOK) return;
#pragma unroll
    for (int k = 0; k < TOPK; k++) {
        int e = g_tok_e[2 * t + k];
        int pos = atomicAdd(&g_cursor[e], 1);
        int row = g_offset[e] + pos;
        g_perm[row] = t;
        g_gw[row] = g_tok_w[2 * t + k];
        g_rowof[2 * t + k] = row;
    }
}

// ==== Fused GEMM A: hid = rna(silu(X@gT) * (X@uT)) ====
// CTA: 128 rows x 64 f.  4 warps (wm 2 x wn 2), warp = 64 rows x 32 f (gate+up).
// B smem tile: rows 0-63 = gate, rows 64-127 = up.
__global__ __launch_bounds__(128, 2) void gemmA_fused() {
    extern __shared__ char smem[];
    __shared__ int toks[BM];
    const int tid = threadIdx.x;
    const int row0 = blockIdx.y * BM;
    if (row0 >= g_offset[NEXP]) return;
    const int f0 = blockIdx.x * 64;
    int e = 0;
    while (g_offset[e + 1] <= row0) e++;

    { int tk = g_perm[row0 + tid]; toks[tid] = tk < 0 ? 0 : tk; }
    __syncthreads();

    const uint32_t sbase = smem_u32(smem);
    const float* bg = g_gater + ((size_t)e * FDIM + f0) * 1024;
    const float* bu = g_upr   + ((size_t)e * FDIM + f0) * 1024;

    auto load_chunk = [&](int kc) {
        const int buf = kc & 1;
        const uint32_t sa = sbase + buf * BUFB;
        const uint32_t sb2 = sa + TILEB;
#pragma unroll
        for (int i = 0; i < 8; i++) {
            const int slot = tid + i * 128;
            const int row = slot >> 3, seg = slot & 7;
            cp16(sa + row * (RSTRIDE * 4) + seg * 16,
                 g_xr + (size_t)toks[row] * 1024 + kc * BK + seg * 4);
            const float* bs = (row < 64)
                ? bg + (size_t)row * 1024 + kc * BK + seg * 4
                : bu + (size_t)(row - 64) * 1024 + kc * BK + seg * 4;
            cp16(sb2 + row * (RSTRIDE * 4) + seg * 16, bs);
        }
        CP_COMMIT();
    };

    const int wid = tid >> 5, lane = tid & 31;
    const int wm = wid & 1, wn = wid >> 1;        // wm: 64-row half; wn: 32-f half
    const int g = lane >> 2, tg = lane & 3;

    float accg[4][4][4], accu[4][4][4];
#pragma unroll
    for (int i = 0; i < 4; i++)
#pragma unroll
        for (int j = 0; j < 4; j++)
#pragma unroll
            for (int k = 0; k < 4; k++) { accg[i][j][k] = 0.f; accu[i][j][k] = 0.f; }

    load_chunk(0);
    for (int kc = 0; kc < NCH; kc++) {
        if (kc + 1 < NCH) { load_chunk(kc + 1); CP_WAIT1(); }
        else              { CP_WAIT0(); }
        __syncthreads();
        const int buf = kc & 1;
        const uint32_t* As = (const uint32_t*)(smem + buf * BUFB);
        const uint32_t* Bs = (const uint32_t*)(smem + buf * BUFB + TILEB);
#pragma unroll
        for (int ks = 0; ks < 4; ks++) {
            const int kb = ks * 8;
            uint32_t af[4][4], bfg[4][2], bfu[4][2];
#pragma unroll
            for (int mt = 0; mt < 4; mt++) {
                const int ar = wm * 64 + mt * 16 + g;
                af[mt][0] = As[ar * RSTRIDE + kb + tg];
                af[mt][1] = As[(ar + 8) * RSTRIDE + kb + tg];
                af[mt][2] = As[ar * RSTRIDE + kb + tg + 4];
                af[mt][3] = As[(ar + 8) * RSTRIDE + kb + tg + 4];
            }
#pragma unroll
            for (int nt = 0; nt < 4; nt++) {
                const int brg = wn * 32 + nt * 8 + g;
                bfg[nt][0] = Bs[brg * RSTRIDE + kb + tg];
                bfg[nt][1] = Bs[brg * RSTRIDE + kb + tg + 4];
                bfu[nt][0] = Bs[(64 + brg) * RSTRIDE + kb + tg];
                bfu[nt][1] = Bs[(64 + brg) * RSTRIDE + kb + tg + 4];
            }
#pragma unroll
            for (int mt = 0; mt < 4; mt++)
#pragma unroll
                for (int nt = 0; nt < 4; nt++) {
                    MMA8(accg[mt][nt], af[mt][0], af[mt][1], af[mt][2], af[mt][3],
                         bfg[nt][0], bfg[nt][1]);
                    MMA8(accu[mt][nt], af[mt][0], af[mt][1], af[mt][2], af[mt][3],
                         bfu[nt][0], bfu[nt][1]);
                }
        }
        __syncthreads();
    }

    // epilogue: SwiGLU + tf32 re-round
#pragma unroll
    for (int mt = 0; mt < 4; mt++) {
        const int r0 = row0 + wm * 64 + mt * 16 + g;
        const int r8 = r0 + 8;
#pragma unroll
        for (int nt = 0; nt < 4; nt++) {
            const int c = f0 + wn * 32 + nt * 8 + 2 * tg;
            float h0 = rna_tf32(__fdividef(accg[mt][nt][0], 1.f + __expf(-accg[mt][nt][0])) * accu[mt][nt][0]);
            float h1 = rna_tf32(__fdividef(accg[mt][nt][1], 1.f + __expf(-accg[mt][nt][1])) * accu[mt][nt][1]);
            float h2 = rna_tf32(__fdividef(accg[mt][nt][2], 1.f + __expf(-accg[mt][nt][2])) * accu[mt][nt][2]);
            float h3 = rna_tf32(__fdividef(accg[mt][nt][3], 1.f + __expf(-accg[mt][nt][3])) * accu[mt][nt][3]);
            *(float2*)(g_hid + (size_t)r0 * FDIM + c) = make_float2(h0, h1);
            *(float2*)(g_hid + (size_t)r8 * FDIM + c) = make_float2(h2, h3);
        }
    }
}

// ==== GEMM B: contrib = gw * (hid @ downT) ====
// CTA: 128 x 128.  4 warps (wm 2 x wn 2), warp = 64 x 64.
__global__ __launch_bounds__(128, 2) void gemmB_kernel() {
    extern __shared__ char smem[];
    const int tid = threadIdx.x;
    const int row0 = blockIdx.y * BM;
    if (row0 >= g_offset[NEXP]) return;
    const int n0 = blockIdx.x * 128;
    int e = 0;
    while (g_offset[e + 1] <= row0) e++;

    const uint32_t sbase = smem_u32(smem);
    const float* bbase = g_downr + ((size_t)e * HDIM + n0) * 1024;

    auto load_chunk = [&](int kc) {
        const int buf = kc & 1;
        const uint32_t sa = sbase + buf * BUFB;
        const uint32_t sb2 = sa + TILEB;
#pragma unroll
        for (int i = 0; i < 8; i++) {
            const int slot = tid + i * 128;
            const int row = slot >> 3, seg = slot & 7;
            cp16(sa + row * (RSTRIDE * 4) + seg * 16,
                 g_hid + (size_t)(row0 + row) * 1024 + kc * BK + seg * 4);
            cp16(sb2 + row * (RSTRIDE * 4) + seg * 16,
                 bbase + (size_t)row * 1024 + kc * BK + seg * 4);
        }
        CP_COMMIT();
    };

    const int wid = tid >> 5, lane = tid & 31;
    const int wm = wid & 1, wn = wid >> 1;
    const int g = lane >> 2, tg = lane & 3;

    float acc[4][8][4];
#pragma unroll
    for (int i = 0; i < 4; i++)
#pragma unroll
        for (int j = 0; j < 8; j++)
#pragma unroll
            for (int k = 0; k < 4; k++) acc[i][j][k] = 0.f;

    load_chunk(0);
    for (int kc = 0; kc < NCH; kc++) {
        if (kc + 1 < NCH) { load_chunk(kc + 1); CP_WAIT1(); }
        else              { CP_WAIT0(); }
        __syncthreads();
        const int buf = kc & 1;
        const uint32_t* As = (const uint32_t*)(smem + buf * BUFB);
        const uint32_t* Bs = (const uint32_t*)(smem + buf * BUFB + TILEB);
#pragma unroll
        for (int ks = 0; ks < 4; ks++) {
            const int kb = ks * 8;
            uint32_t af[4][4], bf[8][2];
#pragma unroll
            for (int mt = 0; mt < 4; mt++) {
                const int ar = wm * 64 + mt * 16 + g;
                af[mt][0] = As[ar * RSTRIDE + kb + tg];
                af[mt][1] = As[(ar + 8) * RSTRIDE + kb + tg];
                af[mt][2] = As[ar * RSTRIDE + kb + tg + 4];
                af[mt][3] = As[(ar + 8) * RSTRIDE + kb + tg + 4];
            }
#pragma unroll
            for (int nt = 0; nt < 8; nt++) {
                const int br = wn * 64 + nt * 8 + g;
                bf[nt][0] = Bs[br * RSTRIDE + kb + tg];
                bf[nt][1] = Bs[br * RSTRIDE + kb + tg + 4];
            }
#pragma unroll
            for (int mt = 0; mt < 4; mt++)
#pragma unroll
                for (int nt = 0; nt < 8; nt++)
                    MMA8(acc[mt][nt], af[mt][0], af[mt][1], af[mt][2], af[mt][3],
                         bf[nt][0], bf[nt][1]);
        }
        __syncthreads();
    }

#pragma unroll
    for (int mt = 0; mt < 4; mt++) {
        const int r0 = row0 + wm * 64 + mt * 16 + g;
        const int r8 = r0 + 8;
        const float w0 = g_gw[r0], w8 = g_gw[r8];
#pragma unroll
        for (int nt = 0; nt < 8; nt++) {
            const int c = n0 + wn * 64 + nt * 8 + 2 * tg;
            *(float2*)(g_contrib + (size_t)r0 * HDIM + c) =
                make_float2(acc[mt][nt][0] * w0, acc[mt][nt][1] * w0);
            *(float2*)(g_contrib + (size_t)r8 * HDIM + c) =
                make_float2(acc[mt][nt][2] * w8, acc[mt][nt][3] * w8);
        }
    }
}

// ---- combine (deterministic) ----
__global__ void combine_kernel(float* __restrict__ out) {
    int idx = blockIdx.x * blockDim.x + threadIdx.x;
    if (idx >= NTOK * (HDIM / 4)) return;
    int n = idx >> 8;
    int hq = (idx & 255) * 4;
    int r0 = g_rowof[2 * n], r1 = g_rowof[2 * n + 1];
    float4 a = *(const float4*)&g_contrib[(size_t)r0 * HDIM + hq];
    float4 b = *(const float4*)&g_contrib[(size_t)r1 * HDIM + hq];
    *(float4*)&out[(size_t)n * HDIM + hq] =
        make_float4(a.x + b.x, a.y + b.y, a.z + b.z, a.w + b.w);
}

// ---- launch ----
extern "C" void kernel_launch(void* const* d_in, const int* in_sizes, int n_in,
                              void* d_out, int out_size) {
    const float* x  = (const float*)d_in[0];
    const float* rw = (const float*)d_in[1];
    const float* gw = (const float*)d_in[2];
    const float* uw = (const float*)d_in[3];
    const float* dw = (const float*)d_in[4];
    float* out = (float*)d_out;
    int wlb = (out_size > NTOK * HDIM) ? 1 : 0;
    float* lb_ptr = out + (size_t)NTOK * HDIM;

    cudaFuncSetAttribute(gemmA_fused, cudaFuncAttributeMaxDynamicSharedMemorySize, SMEM_GEMM);
    cudaFuncSetAttribute(gemmB_kernel, cudaFuncAttributeMaxDynamicSharedMemorySize, SMEM_GEMM);

    float* xr;  cudaGetSymbolAddress((void**)&xr, g_xr);
    float* gr;  cudaGetSymbolAddress((void**)&gr, g_gater);
    float* ur;  cudaGetSymbolAddress((void**)&ur, g_upr);
    float* dr;  cudaGetSymbolAddress((void**)&dr, g_downr);

    round_kernel<<<1024, 256>>>((const float4*)x,  (float4*)xr, NTOK * HDIM / 4);
    round_kernel<<<1024, 256>>>((const float4*)gw, (float4*)gr, NWEIGHT / 4);
    round_kernel<<<1024, 256>>>((const float4*)uw, (float4*)ur, NWEIGHT / 4);
    round_kernel<<<1024, 256>>>((const float4*)dw, (float4*)dr, NWEIGHT / 4);

    init_kernel<<<(PADDED_CAP + 255) / 256, 256>>>();
    router_kernel<<<NTOK / 4, 128>>>(x, rw);
    scan_kernel<<<1, 1>>>(lb_ptr, wlb);
    place_kernel<<<NTOK / 256, 256>>>();

    dim3 gA(FDIM / 64, ROWTILES);                    // (16, 264)
    gemmA_fused<<<gA, 128, SMEM_GEMM>>>();
    dim3 gB(HDIM / 128, ROWTILES);                   // (8, 264)
    gemmB_kernel<<<gB, 128, SMEM_GEMM>>>();

    combine_kernel<<<(NTOK * (HDIM / 4) + 255) / 256, 256>>>(out);
}